// round 6
// baseline (speedup 1.0000x reference)
#include <cuda_runtime.h>
#include <stdint.h>

// Problem constants
#define IN_F   4096
#define OUT_F  11008
#define M_ROWS 4096
#define N_GROUPS 32          // IN_F / 128
#define ALPHA  0.05f

// GEMM tiling
#define BM 128
#define BN 128
#define BK 16

// 180 MB fp32 scratch for the dequantized noisy weight matrix [OUT_F, IN_F]
__device__ float g_W[(size_t)OUT_F * IN_F];

// ---------------------------------------------------------------------------
// f32x2 packed-math helpers (FFMA2 — ptxas never emits this from C++)
// ---------------------------------------------------------------------------
__device__ __forceinline__ void ffma2(unsigned long long& d,
                                      unsigned long long a,
                                      unsigned long long b) {
    asm volatile("fma.rn.f32x2 %0, %1, %2, %0;" : "+l"(d) : "l"(a), "l"(b));
}

__device__ __forceinline__ unsigned long long dup2(float a) {
    unsigned long long d;
    unsigned int u = __float_as_uint(a);
    asm("mov.b64 %0, {%1, %1};" : "=l"(d) : "r"(u));
    return d;
}

__device__ __forceinline__ float2 unpack2(unsigned long long d) {
    unsigned int lo, hi;
    asm("mov.b64 {%0, %1}, %2;" : "=r"(lo), "=r"(hi) : "l"(d));
    float2 r;
    r.x = __uint_as_float(lo);
    r.y = __uint_as_float(hi);
    return r;
}

// ---------------------------------------------------------------------------
// Pass 1: grouped dequant + relative noise, 4 elements per thread
//   w  = (q - zero[g]) * scale[g]
//   wn = w + noise * (ALPHA * |w|)
// ---------------------------------------------------------------------------
__global__ void dequant_kernel(const int4* __restrict__ q4,
                               const float* __restrict__ scales,
                               const float* __restrict__ zeros,
                               const float4* __restrict__ n4) {
    const int tid = blockIdx.x * blockDim.x + threadIdx.x;
    // total quads = OUT_F*IN_F/4 = 11,272,192 ; grid sized exactly
    const int o = tid >> 10;                 // tid*4 / 4096
    const int g = (tid & 1023) >> 5;         // ((tid*4) % 4096) / 128
    const float s  = scales[o * N_GROUPS + g];
    const float zp = zeros[o * N_GROUPS + g];

    const int4   q  = q4[tid];
    const float4 nz = n4[tid];

    float4 wv;
    wv.x = ((float)q.x - zp) * s;
    wv.y = ((float)q.y - zp) * s;
    wv.z = ((float)q.z - zp) * s;
    wv.w = ((float)q.w - zp) * s;

    wv.x = fmaf(ALPHA * fabsf(wv.x), nz.x, wv.x);
    wv.y = fmaf(ALPHA * fabsf(wv.y), nz.y, wv.y);
    wv.z = fmaf(ALPHA * fabsf(wv.z), nz.z, wv.z);
    wv.w = fmaf(ALPHA * fabsf(wv.w), nz.w, wv.w);

    reinterpret_cast<float4*>(g_W)[tid] = wv;
}

// ---------------------------------------------------------------------------
// Pass 2: tiled fp32 GEMM, Y[m,n] = sum_k X[m,k] * W[n,k] + bias[n]
// 128x128 block tile, BK=16, 256 threads, 8x8 per-thread microtile,
// inner product via packed fma.rn.f32x2 (FFMA2).
// ---------------------------------------------------------------------------
__global__ __launch_bounds__(256, 2)
void gemm_kernel(const float* __restrict__ X,
                 const float* __restrict__ bias,
                 float* __restrict__ Y) {
    __shared__ __align__(16) float As[BK][BM];
    __shared__ __align__(16) float Bs[BK][BN];

    const int tid = threadIdx.x;
    const int bm = blockIdx.y * BM;
    const int bn = blockIdx.x * BN;

    const int tx = tid & 15;        // 0..15 -> n direction
    const int ty = tid >> 4;        // 0..15 -> m direction
    const int tm = ty * 8;
    const int tn = tx * 8;

    const float* Aptr = X + (size_t)bm * IN_F;
    const float* Bptr = g_W + (size_t)bn * IN_F;

    unsigned long long c[8][4] = {};   // 8 rows x 4 packed f32x2 = 8x8 fp32

    for (int k0 = 0; k0 < IN_F; k0 += BK) {
        // cooperative load: 2 x float4 per thread per tile (A and B)
        #pragma unroll
        for (int it = 0; it < 2; ++it) {
            const int idx = tid + it * 256;      // 0..511
            const int row = idx >> 2;            // 0..127
            const int c4  = (idx & 3) << 2;      // 0,4,8,12

            const float4 av = *reinterpret_cast<const float4*>(
                Aptr + (size_t)row * IN_F + k0 + c4);
            As[c4 + 0][row] = av.x;
            As[c4 + 1][row] = av.y;
            As[c4 + 2][row] = av.z;
            As[c4 + 3][row] = av.w;

            const float4 bv = *reinterpret_cast<const float4*>(
                Bptr + (size_t)row * IN_F + k0 + c4);
            Bs[c4 + 0][row] = bv.x;
            Bs[c4 + 1][row] = bv.y;
            Bs[c4 + 2][row] = bv.z;
            Bs[c4 + 3][row] = bv.w;
        }
        __syncthreads();

        #pragma unroll
        for (int k = 0; k < BK; ++k) {
            const float4 a0 = *reinterpret_cast<const float4*>(&As[k][tm]);
            const float4 a1 = *reinterpret_cast<const float4*>(&As[k][tm + 4]);
            const ulonglong2 bb0 = *reinterpret_cast<const ulonglong2*>(&Bs[k][tn]);
            const ulonglong2 bb1 = *reinterpret_cast<const ulonglong2*>(&Bs[k][tn + 4]);

            const unsigned long long b[4] = {bb0.x, bb0.y, bb1.x, bb1.y};
            const float a[8] = {a0.x, a0.y, a0.z, a0.w, a1.x, a1.y, a1.z, a1.w};

            #pragma unroll
            for (int i = 0; i < 8; ++i) {
                const unsigned long long ad = dup2(a[i]);
                ffma2(c[i][0], ad, b[0]);
                ffma2(c[i][1], ad, b[1]);
                ffma2(c[i][2], ad, b[2]);
                ffma2(c[i][3], ad, b[3]);
            }
        }
        __syncthreads();
    }

    // epilogue: add bias, vectorized stores
    float bvals[8];
    #pragma unroll
    for (int j = 0; j < 8; ++j) bvals[j] = bias[bn + tn + j];

    #pragma unroll
    for (int i = 0; i < 8; ++i) {
        const float2 p0 = unpack2(c[i][0]);
        const float2 p1 = unpack2(c[i][1]);
        const float2 p2 = unpack2(c[i][2]);
        const float2 p3 = unpack2(c[i][3]);

        float4 o0, o1;
        o0.x = p0.x + bvals[0];
        o0.y = p0.y + bvals[1];
        o0.z = p1.x + bvals[2];
        o0.w = p1.y + bvals[3];
        o1.x = p2.x + bvals[4];
        o1.y = p2.y + bvals[5];
        o1.z = p3.x + bvals[6];
        o1.w = p3.y + bvals[7];

        float* yrow = Y + (size_t)(bm + tm + i) * OUT_F + bn + tn;
        *reinterpret_cast<float4*>(yrow)     = o0;
        *reinterpret_cast<float4*>(yrow + 4) = o1;
    }
}

// ---------------------------------------------------------------------------
// Launch: dequant -> GEMM on the same stream (graph-capturable, alloc-free)
// Inputs (metadata order): x, qweight, scales, zeros, bias, noise
// ---------------------------------------------------------------------------
extern "C" void kernel_launch(void* const* d_in, const int* in_sizes, int n_in,
                              void* d_out, int out_size) {
    const float* x      = (const float*)d_in[0];
    const int*   qw     = (const int*)d_in[1];
    const float* scales = (const float*)d_in[2];
    const float* zeros  = (const float*)d_in[3];
    const float* bias   = (const float*)d_in[4];
    const float* noise  = (const float*)d_in[5];
    float* y = (float*)d_out;

    // OUT_F*IN_F/4 quads / 256 threads = 44032 blocks (exact)
    dequant_kernel<<<44032, 256>>>(
        reinterpret_cast<const int4*>(qw), scales, zeros,
        reinterpret_cast<const float4*>(noise));

    dim3 grid(OUT_F / BN, M_ROWS / BM);   // (86, 32)
    gemm_kernel<<<grid, 256>>>(x, bias, y);
}

// round 8
// speedup vs baseline: 2.7931x; 2.7931x over previous
#include <cuda_runtime.h>
#include <cuda_bf16.h>
#include <stdint.h>

// ---------------------------------------------------------------------------
// Problem constants
// ---------------------------------------------------------------------------
#define IN_F     4096
#define OUT_F    11008
#define M_ROWS   4096
#define N_GROUPS 32
#define ALPHA    0.05f

// GEMM tiling (legacy mma.sync path — tcgen05 unavailable at .target sm_103)
#define BM 128
#define BN 128
#define BK 64                         // bf16 K elems per chunk (128B rows)
#define KCHUNKS (IN_F / BK)           // 64 physical chunks
#define VCHUNKS (3 * KCHUNKS)         // 192 virtual chunks (3-term split)
#define STAGES 4

#define A_TILE 16384                  // 128 rows * 128 B
#define B_TILE 16384                  // 128 rows * 128 B
#define STAGE_BYTES (A_TILE + B_TILE) // 32 KB
#define SMEM_BYTES (STAGES * STAGE_BYTES + 256)

// ---------------------------------------------------------------------------
// Split-precision operand scratch (static device arrays — alloc-free)
// ---------------------------------------------------------------------------
__device__ __nv_bfloat16 g_Xhi[(size_t)M_ROWS * IN_F];
__device__ __nv_bfloat16 g_Xlo[(size_t)M_ROWS * IN_F];
__device__ __nv_bfloat16 g_Whi[(size_t)OUT_F * IN_F];
__device__ __nv_bfloat16 g_Wlo[(size_t)OUT_F * IN_F];

// ---------------------------------------------------------------------------
// PTX helpers (all plain-sm_103-safe: cp.async, ldmatrix, mma.sync)
// ---------------------------------------------------------------------------
__device__ __forceinline__ uint32_t smem_u32(const void* p) {
    uint32_t a;
    asm("{ .reg .u64 t; cvta.to.shared.u64 t, %1; cvt.u32.u64 %0, t; }"
        : "=r"(a) : "l"(p));
    return a;
}

__device__ __forceinline__ void cp16(uint32_t dst, const void* src) {
    asm volatile("cp.async.cg.shared.global.L2::128B [%0], [%1], 16;"
                 :: "r"(dst), "l"(src));
}
#define CP_COMMIT() asm volatile("cp.async.commit_group;")
#define CP_WAIT2()  asm volatile("cp.async.wait_group %0;" :: "n"(STAGES - 2))

__device__ __forceinline__ void ldsm4(uint32_t* r, uint32_t addr) {
    asm volatile("ldmatrix.sync.aligned.m8n8.x4.shared.b16 {%0,%1,%2,%3}, [%4];"
                 : "=r"(r[0]), "=r"(r[1]), "=r"(r[2]), "=r"(r[3]) : "r"(addr));
}

__device__ __forceinline__ void mma16816(float* c, const uint32_t* a,
                                         uint32_t b0, uint32_t b1) {
    asm volatile(
        "mma.sync.aligned.m16n8k16.row.col.f32.bf16.bf16.f32 "
        "{%0,%1,%2,%3}, {%4,%5,%6,%7}, {%8,%9}, {%0,%1,%2,%3};"
        : "+f"(c[0]), "+f"(c[1]), "+f"(c[2]), "+f"(c[3])
        : "r"(a[0]), "r"(a[1]), "r"(a[2]), "r"(a[3]), "r"(b0), "r"(b1));
}

// SW128 swizzle on (row*128 + colb), colb < 128:
// simplifies to row*128 + (colb ^ ((row & 7) << 4))
__device__ __forceinline__ uint32_t swz(int row, int colb) {
    return (uint32_t)(row * 128 + (colb ^ ((row & 7) << 4)));
}

// ---------------------------------------------------------------------------
// Prep 1: split X into bf16 hi + bf16 residual
// ---------------------------------------------------------------------------
__global__ void x_split_kernel(const float4* __restrict__ x4) {
    const int tid = blockIdx.x * blockDim.x + threadIdx.x;
    const float4 v = x4[tid];

    __nv_bfloat16 hx = __float2bfloat16_rn(v.x);
    __nv_bfloat16 hy = __float2bfloat16_rn(v.y);
    __nv_bfloat16 hz = __float2bfloat16_rn(v.z);
    __nv_bfloat16 hw = __float2bfloat16_rn(v.w);

    __nv_bfloat16 lx = __float2bfloat16_rn(v.x - __bfloat162float(hx));
    __nv_bfloat16 ly = __float2bfloat16_rn(v.y - __bfloat162float(hy));
    __nv_bfloat16 lz = __float2bfloat16_rn(v.z - __bfloat162float(hz));
    __nv_bfloat16 lw = __float2bfloat16_rn(v.w - __bfloat162float(hw));

    __nv_bfloat162* H = reinterpret_cast<__nv_bfloat162*>(g_Xhi);
    __nv_bfloat162* L = reinterpret_cast<__nv_bfloat162*>(g_Xlo);
    __nv_bfloat162 p;
    p.x = hx; p.y = hy; H[(size_t)tid * 2 + 0] = p;
    p.x = hz; p.y = hw; H[(size_t)tid * 2 + 1] = p;
    p.x = lx; p.y = ly; L[(size_t)tid * 2 + 0] = p;
    p.x = lz; p.y = lw; L[(size_t)tid * 2 + 1] = p;
}

// ---------------------------------------------------------------------------
// Prep 2: grouped dequant + relative noise + bf16 hi/lo split
// ---------------------------------------------------------------------------
__global__ void dequant_split_kernel(const int4* __restrict__ q4,
                                     const float* __restrict__ scales,
                                     const float* __restrict__ zeros,
                                     const float4* __restrict__ n4) {
    const int tid = blockIdx.x * blockDim.x + threadIdx.x;
    const int o = tid >> 10;
    const int g = (tid & 1023) >> 5;
    const float s  = scales[o * N_GROUPS + g];
    const float zp = zeros[o * N_GROUPS + g];

    const int4   q  = q4[tid];
    const float4 nz = n4[tid];

    float4 wv;
    wv.x = ((float)q.x - zp) * s;
    wv.y = ((float)q.y - zp) * s;
    wv.z = ((float)q.z - zp) * s;
    wv.w = ((float)q.w - zp) * s;

    wv.x = fmaf(ALPHA * fabsf(wv.x), nz.x, wv.x);
    wv.y = fmaf(ALPHA * fabsf(wv.y), nz.y, wv.y);
    wv.z = fmaf(ALPHA * fabsf(wv.z), nz.z, wv.z);
    wv.w = fmaf(ALPHA * fabsf(wv.w), nz.w, wv.w);

    __nv_bfloat16 hx = __float2bfloat16_rn(wv.x);
    __nv_bfloat16 hy = __float2bfloat16_rn(wv.y);
    __nv_bfloat16 hz = __float2bfloat16_rn(wv.z);
    __nv_bfloat16 hw = __float2bfloat16_rn(wv.w);

    __nv_bfloat16 lx = __float2bfloat16_rn(wv.x - __bfloat162float(hx));
    __nv_bfloat16 ly = __float2bfloat16_rn(wv.y - __bfloat162float(hy));
    __nv_bfloat16 lz = __float2bfloat16_rn(wv.z - __bfloat162float(hz));
    __nv_bfloat16 lw = __float2bfloat16_rn(wv.w - __bfloat162float(hw));

    __nv_bfloat162* H = reinterpret_cast<__nv_bfloat162*>(g_Whi);
    __nv_bfloat162* L = reinterpret_cast<__nv_bfloat162*>(g_Wlo);
    __nv_bfloat162 p;
    p.x = hx; p.y = hy; H[(size_t)tid * 2 + 0] = p;
    p.x = hz; p.y = hw; H[(size_t)tid * 2 + 1] = p;
    p.x = lx; p.y = ly; L[(size_t)tid * 2 + 0] = p;
    p.x = lz; p.y = lw; L[(size_t)tid * 2 + 1] = p;
}

// ---------------------------------------------------------------------------
// Load one stage: A tile 128x64 bf16 + B tile 128x64 bf16, SW128 swizzled.
// Virtual chunk c = kc*3 + phase; phase 0:(Xhi,Whi) 1:(Xlo,Whi) 2:(Xhi,Wlo)
// ---------------------------------------------------------------------------
__device__ __forceinline__ void load_stage(uint32_t sb, int chunk, int bm,
                                           int bn, int tid) {
    const int kc = chunk / 3;
    const int ph = chunk - kc * 3;
    const __nv_bfloat16* __restrict__ A = (ph == 1) ? g_Xlo : g_Xhi;
    const __nv_bfloat16* __restrict__ B = (ph == 2) ? g_Wlo : g_Whi;
    const int kk = kc * BK;

    #pragma unroll
    for (int j = 0; j < 4; ++j) {
        const int i = tid + j * 256;           // 0..1023
        const int row = i >> 3, c16 = i & 7;
        cp16(sb + swz(row, c16 * 16),
             A + (size_t)(bm + row) * IN_F + kk + c16 * 8);
    }
    #pragma unroll
    for (int j = 0; j < 4; ++j) {
        const int i = tid + j * 256;
        const int row = i >> 3, c16 = i & 7;
        cp16(sb + A_TILE + swz(row, c16 * 16),
             B + (size_t)(bn + row) * IN_F + kk + c16 * 8);
    }
    CP_COMMIT();
}

// ---------------------------------------------------------------------------
// GEMM: Y[m,n] = sum over 192 virtual chunks, fp32 acc in registers.
// 8 warps: 4 (m) x 2 (n); warp tile 32m x 64n via m16n8k16.
// ---------------------------------------------------------------------------
__global__ __launch_bounds__(256, 1)
void gemm_mma_kernel(const float* __restrict__ bias, float* __restrict__ Y) {
    extern __shared__ char smem[];
    const int tid = threadIdx.x;
    const int wid = tid >> 5;
    const int lid = tid & 31;
    const int wm = wid & 3;          // warp m index (0..3)
    const int wn = wid >> 2;         // warp n index (0..1)
    const int bm = blockIdx.y * BM;
    const int bn = blockIdx.x * BN;

    const uint32_t tiles = (smem_u32(smem) + 127u) & ~127u;

    float acc[2][8][4];
    #pragma unroll
    for (int i = 0; i < 2; ++i)
        #pragma unroll
        for (int j = 0; j < 8; ++j)
            #pragma unroll
            for (int k = 0; k < 4; ++k) acc[i][j][k] = 0.0f;

    // Prologue: fill STAGES-1 stages
    #pragma unroll
    for (int s = 0; s < STAGES - 1; ++s)
        load_stage(tiles + s * STAGE_BYTES, s, bm, bn, tid);

    // Per-thread fragment offsets within tile (swizzled, colb-independent XOR)
    const int arow = wm * 32 + (lid & 15);           // + im*16
    const int asel = (lid >> 4) << 4;                // 0 or 16 bytes
    const int brow = wn * 64 + ((lid >> 4) << 3) + (lid & 7);  // + jn2*16
    const int bsel = ((lid >> 3) & 1) << 4;

    for (int c = 0; c < VCHUNKS; ++c) {
        CP_WAIT2();
        __syncthreads();

        const int nc = c + STAGES - 1;
        if (nc < VCHUNKS)
            load_stage(tiles + (nc % STAGES) * STAGE_BYTES, nc, bm, bn, tid);
        else
            CP_COMMIT();   // keep group count aligned for wait_group

        const uint32_t sA = tiles + (c % STAGES) * STAGE_BYTES;
        const uint32_t sB = sA + A_TILE;

        #pragma unroll
        for (int ks = 0; ks < 4; ++ks) {
            uint32_t a[2][4];
            #pragma unroll
            for (int im = 0; im < 2; ++im)
                ldsm4(a[im], sA + swz(arow + im * 16, ks * 32 + asel));

            uint32_t b[4][4];
            #pragma unroll
            for (int j2 = 0; j2 < 4; ++j2)
                ldsm4(b[j2], sB + swz(brow + j2 * 16, ks * 32 + bsel));

            #pragma unroll
            for (int im = 0; im < 2; ++im)
                #pragma unroll
                for (int jn = 0; jn < 8; ++jn)
                    mma16816(acc[im][jn], a[im],
                             b[jn >> 1][(jn & 1) * 2],
                             b[jn >> 1][(jn & 1) * 2 + 1]);
        }
    }

    // Epilogue: add bias, store fp32 (float2 per half-fragment)
    const int m0 = bm + wm * 32 + (lid >> 2);
    const int n0 = bn + wn * 64 + (lid & 3) * 2;
    #pragma unroll
    for (int im = 0; im < 2; ++im) {
        #pragma unroll
        for (int jn = 0; jn < 8; ++jn) {
            const int m = m0 + im * 16;
            const int n = n0 + jn * 8;
            const float b0 = __ldg(bias + n);
            const float b1 = __ldg(bias + n + 1);
            float2 v0, v1;
            v0.x = acc[im][jn][0] + b0; v0.y = acc[im][jn][1] + b1;
            v1.x = acc[im][jn][2] + b0; v1.y = acc[im][jn][3] + b1;
            *reinterpret_cast<float2*>(Y + (size_t)m * OUT_F + n)       = v0;
            *reinterpret_cast<float2*>(Y + (size_t)(m + 8) * OUT_F + n) = v1;
        }
    }
}

// ---------------------------------------------------------------------------
// Launch (graph-capturable, alloc-free)
// Inputs (metadata order): x, qweight, scales, zeros, bias, noise
// ---------------------------------------------------------------------------
extern "C" void kernel_launch(void* const* d_in, const int* in_sizes, int n_in,
                              void* d_out, int out_size) {
    const float* x      = (const float*)d_in[0];
    const int*   qw     = (const int*)d_in[1];
    const float* scales = (const float*)d_in[2];
    const float* zeros  = (const float*)d_in[3];
    const float* bias   = (const float*)d_in[4];
    const float* noise  = (const float*)d_in[5];
    float* y = (float*)d_out;

    x_split_kernel<<<16384, 256>>>(reinterpret_cast<const float4*>(x));

    dequant_split_kernel<<<44032, 256>>>(
        reinterpret_cast<const int4*>(qw), scales, zeros,
        reinterpret_cast<const float4*>(noise));

    cudaFuncSetAttribute(gemm_mma_kernel,
                         cudaFuncAttributeMaxDynamicSharedMemorySize, SMEM_BYTES);
    dim3 grid(OUT_F / BN, M_ROWS / BM);   // (86, 32)
    gemm_mma_kernel<<<grid, 256, SMEM_BYTES>>>(bias, y);
}

// round 9
// speedup vs baseline: 3.3457x; 1.1979x over previous
#include <cuda_runtime.h>
#include <cuda_bf16.h>
#include <stdint.h>

// ---------------------------------------------------------------------------
// Problem constants
// ---------------------------------------------------------------------------
#define IN_F     4096
#define OUT_F    11008
#define M_ROWS   4096
#define N_GROUPS 32
#define ALPHA    0.05f

// GEMM tiling (legacy mma.sync path — tcgen05 unavailable at .target sm_103)
#define BM 128
#define BN 128
#define BK 64                         // bf16 K elems per chunk (128B rows)
#define KCHUNKS (IN_F / BK)           // 64 physical chunks
#define STAGES 3

#define TILE_B   16384                // 128 rows * 128 B
#define OFF_AHI  0
#define OFF_ALO  16384
#define OFF_BHI  32768
#define OFF_BLO  49152
#define STAGE_BYTES (4 * TILE_B)      // 64 KB: Ahi, Alo, Bhi, Blo
#define SMEM_BYTES (STAGES * STAGE_BYTES + 256)

// ---------------------------------------------------------------------------
// Split-precision operand scratch (static device arrays — alloc-free)
// ---------------------------------------------------------------------------
__device__ __nv_bfloat16 g_Xhi[(size_t)M_ROWS * IN_F];
__device__ __nv_bfloat16 g_Xlo[(size_t)M_ROWS * IN_F];
__device__ __nv_bfloat16 g_Whi[(size_t)OUT_F * IN_F];
__device__ __nv_bfloat16 g_Wlo[(size_t)OUT_F * IN_F];

// ---------------------------------------------------------------------------
// PTX helpers (plain-sm_103-safe: cp.async, ldmatrix, mma.sync)
// ---------------------------------------------------------------------------
__device__ __forceinline__ uint32_t smem_u32(const void* p) {
    uint32_t a;
    asm("{ .reg .u64 t; cvta.to.shared.u64 t, %1; cvt.u32.u64 %0, t; }"
        : "=r"(a) : "l"(p));
    return a;
}

__device__ __forceinline__ void cp16(uint32_t dst, const void* src) {
    asm volatile("cp.async.cg.shared.global.L2::128B [%0], [%1], 16;"
                 :: "r"(dst), "l"(src));
}
#define CP_COMMIT() asm volatile("cp.async.commit_group;")
#define CP_WAIT()   asm volatile("cp.async.wait_group %0;" :: "n"(STAGES - 2))

__device__ __forceinline__ void ldsm4(uint32_t* r, uint32_t addr) {
    asm volatile("ldmatrix.sync.aligned.m8n8.x4.shared.b16 {%0,%1,%2,%3}, [%4];"
                 : "=r"(r[0]), "=r"(r[1]), "=r"(r[2]), "=r"(r[3]) : "r"(addr));
}

__device__ __forceinline__ void mma16816(float* c, const uint32_t* a,
                                         uint32_t b0, uint32_t b1) {
    asm volatile(
        "mma.sync.aligned.m16n8k16.row.col.f32.bf16.bf16.f32 "
        "{%0,%1,%2,%3}, {%4,%5,%6,%7}, {%8,%9}, {%0,%1,%2,%3};"
        : "+f"(c[0]), "+f"(c[1]), "+f"(c[2]), "+f"(c[3])
        : "r"(a[0]), "r"(a[1]), "r"(a[2]), "r"(a[3]), "r"(b0), "r"(b1));
}

// SW128 swizzle on (row*128 + colb), colb < 128:
// simplifies to row*128 + (colb ^ ((row & 7) << 4))
__device__ __forceinline__ uint32_t swz(int row, int colb) {
    return (uint32_t)(row * 128 + (colb ^ ((row & 7) << 4)));
}

// ---------------------------------------------------------------------------
// Prep 1: split X into bf16 hi + bf16 residual
// ---------------------------------------------------------------------------
__global__ void x_split_kernel(const float4* __restrict__ x4) {
    const int tid = blockIdx.x * blockDim.x + threadIdx.x;
    const float4 v = x4[tid];

    __nv_bfloat16 hx = __float2bfloat16_rn(v.x);
    __nv_bfloat16 hy = __float2bfloat16_rn(v.y);
    __nv_bfloat16 hz = __float2bfloat16_rn(v.z);
    __nv_bfloat16 hw = __float2bfloat16_rn(v.w);

    __nv_bfloat16 lx = __float2bfloat16_rn(v.x - __bfloat162float(hx));
    __nv_bfloat16 ly = __float2bfloat16_rn(v.y - __bfloat162float(hy));
    __nv_bfloat16 lz = __float2bfloat16_rn(v.z - __bfloat162float(hz));
    __nv_bfloat16 lw = __float2bfloat16_rn(v.w - __bfloat162float(hw));

    __nv_bfloat162* H = reinterpret_cast<__nv_bfloat162*>(g_Xhi);
    __nv_bfloat162* L = reinterpret_cast<__nv_bfloat162*>(g_Xlo);
    __nv_bfloat162 p;
    p.x = hx; p.y = hy; H[(size_t)tid * 2 + 0] = p;
    p.x = hz; p.y = hw; H[(size_t)tid * 2 + 1] = p;
    p.x = lx; p.y = ly; L[(size_t)tid * 2 + 0] = p;
    p.x = lz; p.y = lw; L[(size_t)tid * 2 + 1] = p;
}

// ---------------------------------------------------------------------------
// Prep 2: grouped dequant + relative noise + bf16 hi/lo split
// ---------------------------------------------------------------------------
__global__ void dequant_split_kernel(const int4* __restrict__ q4,
                                     const float* __restrict__ scales,
                                     const float* __restrict__ zeros,
                                     const float4* __restrict__ n4) {
    const int tid = blockIdx.x * blockDim.x + threadIdx.x;
    const int o = tid >> 10;
    const int g = (tid & 1023) >> 5;
    const float s  = scales[o * N_GROUPS + g];
    const float zp = zeros[o * N_GROUPS + g];

    const int4   q  = q4[tid];
    const float4 nz = n4[tid];

    float4 wv;
    wv.x = ((float)q.x - zp) * s;
    wv.y = ((float)q.y - zp) * s;
    wv.z = ((float)q.z - zp) * s;
    wv.w = ((float)q.w - zp) * s;

    wv.x = fmaf(ALPHA * fabsf(wv.x), nz.x, wv.x);
    wv.y = fmaf(ALPHA * fabsf(wv.y), nz.y, wv.y);
    wv.z = fmaf(ALPHA * fabsf(wv.z), nz.z, wv.z);
    wv.w = fmaf(ALPHA * fabsf(wv.w), nz.w, wv.w);

    __nv_bfloat16 hx = __float2bfloat16_rn(wv.x);
    __nv_bfloat16 hy = __float2bfloat16_rn(wv.y);
    __nv_bfloat16 hz = __float2bfloat16_rn(wv.z);
    __nv_bfloat16 hw = __float2bfloat16_rn(wv.w);

    __nv_bfloat16 lx = __float2bfloat16_rn(wv.x - __bfloat162float(hx));
    __nv_bfloat16 ly = __float2bfloat16_rn(wv.y - __bfloat162float(hy));
    __nv_bfloat16 lz = __float2bfloat16_rn(wv.z - __bfloat162float(hz));
    __nv_bfloat16 lw = __float2bfloat16_rn(wv.w - __bfloat162float(hw));

    __nv_bfloat162* H = reinterpret_cast<__nv_bfloat162*>(g_Whi);
    __nv_bfloat162* L = reinterpret_cast<__nv_bfloat162*>(g_Wlo);
    __nv_bfloat162 p;
    p.x = hx; p.y = hy; H[(size_t)tid * 2 + 0] = p;
    p.x = hz; p.y = hw; H[(size_t)tid * 2 + 1] = p;
    p.x = lx; p.y = ly; L[(size_t)tid * 2 + 0] = p;
    p.x = lz; p.y = lw; L[(size_t)tid * 2 + 1] = p;
}

// ---------------------------------------------------------------------------
// Load one stage: 4 tiles (Ahi, Alo, Bhi, Blo), each 128x64 bf16, SW128.
// 16 x cp16 per thread.
// ---------------------------------------------------------------------------
__device__ __forceinline__ void load_stage(uint32_t sb, int kc, int bm, int bn,
                                           int tid) {
    const int kk = kc * BK;
    #pragma unroll
    for (int j = 0; j < 4; ++j) {
        const int i = tid + j * 256;            // 0..1023
        const int row = i >> 3, c16 = i & 7;
        const uint32_t sw = swz(row, c16 * 16);
        const size_t gA = (size_t)(bm + row) * IN_F + kk + c16 * 8;
        const size_t gB = (size_t)(bn + row) * IN_F + kk + c16 * 8;
        cp16(sb + OFF_AHI + sw, g_Xhi + gA);
        cp16(sb + OFF_ALO + sw, g_Xlo + gA);
        cp16(sb + OFF_BHI + sw, g_Whi + gB);
        cp16(sb + OFF_BLO + sw, g_Wlo + gB);
    }
    CP_COMMIT();
}

// ---------------------------------------------------------------------------
// GEMM: fp32 acc in registers. Per physical K-chunk, 3 split-terms reuse one
// 4-tile stage: acc += Ahi*Bhi + Alo*Bhi + Ahi*Blo.
// 8 warps: 4 (m) x 2 (n); warp tile 32m x 64n via m16n8k16.
// Grid: blockIdx.x = m-tile (fast) so a wave shares W tiles in L2.
// ---------------------------------------------------------------------------
__global__ __launch_bounds__(256, 1)
void gemm_mma_kernel(const float* __restrict__ bias, float* __restrict__ Y) {
    extern __shared__ char smem[];
    const int tid = threadIdx.x;
    const int wid = tid >> 5;
    const int lid = tid & 31;
    const int wm = wid & 3;          // warp m index (0..3)
    const int wn = wid >> 2;         // warp n index (0..1)
    const int bm = blockIdx.x * BM;  // m fast -> W tiles shared across wave
    const int bn = blockIdx.y * BN;

    const uint32_t tiles = (smem_u32(smem) + 127u) & ~127u;

    float acc[2][8][4];
    #pragma unroll
    for (int i = 0; i < 2; ++i)
        #pragma unroll
        for (int j = 0; j < 8; ++j)
            #pragma unroll
            for (int k = 0; k < 4; ++k) acc[i][j][k] = 0.0f;

    // Prologue: fill STAGES-1 stages
    #pragma unroll
    for (int s = 0; s < STAGES - 1; ++s)
        load_stage(tiles + s * STAGE_BYTES, s, bm, bn, tid);

    // Per-thread fragment coordinates (swizzle XOR is colb-independent)
    const int arow = wm * 32 + (lid & 15);                     // + im*16
    const int asel = (lid >> 4) << 4;                          // 0 or 16 B
    const int brow = wn * 64 + ((lid >> 4) << 3) + (lid & 7);  // + j2*16
    const int bsel = ((lid >> 3) & 1) << 4;

    for (int kc = 0; kc < KCHUNKS; ++kc) {
        CP_WAIT();
        __syncthreads();

        const int nc = kc + STAGES - 1;
        if (nc < KCHUNKS)
            load_stage(tiles + (nc % STAGES) * STAGE_BYTES, nc, bm, bn, tid);
        else
            CP_COMMIT();   // keep group count aligned for wait_group

        const uint32_t sb = tiles + (kc % STAGES) * STAGE_BYTES;

        #pragma unroll
        for (int ks = 0; ks < 4; ++ks) {
            uint32_t ah[2][4], al[2][4];
            #pragma unroll
            for (int im = 0; im < 2; ++im) {
                const uint32_t aoff = swz(arow + im * 16, ks * 32 + asel);
                ldsm4(ah[im], sb + OFF_AHI + aoff);
                ldsm4(al[im], sb + OFF_ALO + aoff);
            }
            uint32_t bh[4][4], bl[4][4];
            #pragma unroll
            for (int j2 = 0; j2 < 4; ++j2) {
                const uint32_t boff = swz(brow + j2 * 16, ks * 32 + bsel);
                ldsm4(bh[j2], sb + OFF_BHI + boff);
                ldsm4(bl[j2], sb + OFF_BLO + boff);
            }

            #pragma unroll
            for (int im = 0; im < 2; ++im) {
                #pragma unroll
                for (int jn = 0; jn < 8; ++jn) {
                    const uint32_t bh0 = bh[jn >> 1][(jn & 1) * 2];
                    const uint32_t bh1 = bh[jn >> 1][(jn & 1) * 2 + 1];
                    const uint32_t bl0 = bl[jn >> 1][(jn & 1) * 2];
                    const uint32_t bl1 = bl[jn >> 1][(jn & 1) * 2 + 1];
                    mma16816(acc[im][jn], ah[im], bh0, bh1);   // hi*hi
                    mma16816(acc[im][jn], al[im], bh0, bh1);   // lo*hi
                    mma16816(acc[im][jn], ah[im], bl0, bl1);   // hi*lo
                }
            }
        }
    }

    // Epilogue: add bias, store fp32
    const int m0 = bm + wm * 32 + (lid >> 2);
    const int n0 = bn + wn * 64 + (lid & 3) * 2;
    #pragma unroll
    for (int im = 0; im < 2; ++im) {
        #pragma unroll
        for (int jn = 0; jn < 8; ++jn) {
            const int m = m0 + im * 16;
            const int n = n0 + jn * 8;
            const float b0 = __ldg(bias + n);
            const float b1 = __ldg(bias + n + 1);
            float2 v0, v1;
            v0.x = acc[im][jn][0] + b0; v0.y = acc[im][jn][1] + b1;
            v1.x = acc[im][jn][2] + b0; v1.y = acc[im][jn][3] + b1;
            *reinterpret_cast<float2*>(Y + (size_t)m * OUT_F + n)       = v0;
            *reinterpret_cast<float2*>(Y + (size_t)(m + 8) * OUT_F + n) = v1;
        }
    }
}

// ---------------------------------------------------------------------------
// Launch (graph-capturable, alloc-free)
// Inputs (metadata order): x, qweight, scales, zeros, bias, noise
// ---------------------------------------------------------------------------
extern "C" void kernel_launch(void* const* d_in, const int* in_sizes, int n_in,
                              void* d_out, int out_size) {
    const float* x      = (const float*)d_in[0];
    const int*   qw     = (const int*)d_in[1];
    const float* scales = (const float*)d_in[2];
    const float* zeros  = (const float*)d_in[3];
    const float* bias   = (const float*)d_in[4];
    const float* noise  = (const float*)d_in[5];
    float* y = (float*)d_out;

    x_split_kernel<<<16384, 256>>>(reinterpret_cast<const float4*>(x));

    dequant_split_kernel<<<44032, 256>>>(
        reinterpret_cast<const int4*>(qw), scales, zeros,
        reinterpret_cast<const float4*>(noise));

    cudaFuncSetAttribute(gemm_mma_kernel,
                         cudaFuncAttributeMaxDynamicSharedMemorySize, SMEM_BYTES);
    dim3 grid(M_ROWS / BM, OUT_F / BN);   // (32, 86) — m-tile fast
    gemm_mma_kernel<<<grid, 256, SMEM_BYTES>>>(bias, y);
}

// round 10
// speedup vs baseline: 3.3460x; 1.0001x over previous
#include <cuda_runtime.h>
#include <cuda_bf16.h>
#include <stdint.h>

// ---------------------------------------------------------------------------
// Problem constants
// ---------------------------------------------------------------------------
#define IN_F     4096
#define OUT_F    11008
#define M_ROWS   4096
#define N_GROUPS 32
#define ALPHA    0.05f

// GEMM tiling (legacy mma.sync path — tcgen05 unavailable at .target sm_103)
#define BM 128
#define BN 128
#define BK 64                         // bf16 K elems per chunk (128B rows)
#define KCHUNKS (IN_F / BK)           // 64 physical chunks
#define STAGES 3

#define TILE_B   16384                // 128 rows * 128 B
#define OFF_AHI  0
#define OFF_ALO  16384
#define OFF_BHI  32768
#define OFF_BLO  49152
#define STAGE_BYTES (4 * TILE_B)      // 64 KB: Ahi, Alo, Bhi, Blo
#define SMEM_BYTES (STAGES * STAGE_BYTES + 256)

// ---------------------------------------------------------------------------
// Split-precision operand scratch (static device arrays — alloc-free)
// ---------------------------------------------------------------------------
__device__ __nv_bfloat16 g_Xhi[(size_t)M_ROWS * IN_F];
__device__ __nv_bfloat16 g_Xlo[(size_t)M_ROWS * IN_F];
__device__ __nv_bfloat16 g_Whi[(size_t)OUT_F * IN_F];
__device__ __nv_bfloat16 g_Wlo[(size_t)OUT_F * IN_F];

// ---------------------------------------------------------------------------
// PTX helpers (plain-sm_103-safe: cp.async, ldmatrix, mma.sync)
// ---------------------------------------------------------------------------
__device__ __forceinline__ uint32_t smem_u32(const void* p) {
    uint32_t a;
    asm("{ .reg .u64 t; cvta.to.shared.u64 t, %1; cvt.u32.u64 %0, t; }"
        : "=r"(a) : "l"(p));
    return a;
}

__device__ __forceinline__ void cp16(uint32_t dst, const void* src) {
    asm volatile("cp.async.cg.shared.global.L2::128B [%0], [%1], 16;"
                 :: "r"(dst), "l"(src));
}
#define CP_COMMIT() asm volatile("cp.async.commit_group;")
#define CP_WAIT()   asm volatile("cp.async.wait_group %0;" :: "n"(STAGES - 2))

__device__ __forceinline__ void ldsm4(uint32_t* r, uint32_t addr) {
    asm volatile("ldmatrix.sync.aligned.m8n8.x4.shared.b16 {%0,%1,%2,%3}, [%4];"
                 : "=r"(r[0]), "=r"(r[1]), "=r"(r[2]), "=r"(r[3]) : "r"(addr));
}

// NOTE: non-volatile — pure register op; lets ptxas schedule freely.
__device__ __forceinline__ void mma16816(float* c, const uint32_t* a,
                                         uint32_t b0, uint32_t b1) {
    asm("mma.sync.aligned.m16n8k16.row.col.f32.bf16.bf16.f32 "
        "{%0,%1,%2,%3}, {%4,%5,%6,%7}, {%8,%9}, {%0,%1,%2,%3};"
        : "+f"(c[0]), "+f"(c[1]), "+f"(c[2]), "+f"(c[3])
        : "r"(a[0]), "r"(a[1]), "r"(a[2]), "r"(a[3]), "r"(b0), "r"(b1));
}

// SW128 swizzle on (row*128 + colb), colb < 128:
// simplifies to row*128 + (colb ^ ((row & 7) << 4))
__device__ __forceinline__ uint32_t swz(int row, int colb) {
    return (uint32_t)(row * 128 + (colb ^ ((row & 7) << 4)));
}

// ---------------------------------------------------------------------------
// Prep 1: split X into bf16 hi + bf16 residual
// ---------------------------------------------------------------------------
__global__ void x_split_kernel(const float4* __restrict__ x4) {
    const int tid = blockIdx.x * blockDim.x + threadIdx.x;
    const float4 v = x4[tid];

    __nv_bfloat16 hx = __float2bfloat16_rn(v.x);
    __nv_bfloat16 hy = __float2bfloat16_rn(v.y);
    __nv_bfloat16 hz = __float2bfloat16_rn(v.z);
    __nv_bfloat16 hw = __float2bfloat16_rn(v.w);

    __nv_bfloat16 lx = __float2bfloat16_rn(v.x - __bfloat162float(hx));
    __nv_bfloat16 ly = __float2bfloat16_rn(v.y - __bfloat162float(hy));
    __nv_bfloat16 lz = __float2bfloat16_rn(v.z - __bfloat162float(hz));
    __nv_bfloat16 lw = __float2bfloat16_rn(v.w - __bfloat162float(hw));

    __nv_bfloat162* H = reinterpret_cast<__nv_bfloat162*>(g_Xhi);
    __nv_bfloat162* L = reinterpret_cast<__nv_bfloat162*>(g_Xlo);
    __nv_bfloat162 p;
    p.x = hx; p.y = hy; H[(size_t)tid * 2 + 0] = p;
    p.x = hz; p.y = hw; H[(size_t)tid * 2 + 1] = p;
    p.x = lx; p.y = ly; L[(size_t)tid * 2 + 0] = p;
    p.x = lz; p.y = lw; L[(size_t)tid * 2 + 1] = p;
}

// ---------------------------------------------------------------------------
// Prep 2: grouped dequant + relative noise + bf16 hi/lo split
// ---------------------------------------------------------------------------
__global__ void dequant_split_kernel(const int4* __restrict__ q4,
                                     const float* __restrict__ scales,
                                     const float* __restrict__ zeros,
                                     const float4* __restrict__ n4) {
    const int tid = blockIdx.x * blockDim.x + threadIdx.x;
    const int o = tid >> 10;
    const int g = (tid & 1023) >> 5;
    const float s  = scales[o * N_GROUPS + g];
    const float zp = zeros[o * N_GROUPS + g];

    const int4   q  = q4[tid];
    const float4 nz = n4[tid];

    float4 wv;
    wv.x = ((float)q.x - zp) * s;
    wv.y = ((float)q.y - zp) * s;
    wv.z = ((float)q.z - zp) * s;
    wv.w = ((float)q.w - zp) * s;

    wv.x = fmaf(ALPHA * fabsf(wv.x), nz.x, wv.x);
    wv.y = fmaf(ALPHA * fabsf(wv.y), nz.y, wv.y);
    wv.z = fmaf(ALPHA * fabsf(wv.z), nz.z, wv.z);
    wv.w = fmaf(ALPHA * fabsf(wv.w), nz.w, wv.w);

    __nv_bfloat16 hx = __float2bfloat16_rn(wv.x);
    __nv_bfloat16 hy = __float2bfloat16_rn(wv.y);
    __nv_bfloat16 hz = __float2bfloat16_rn(wv.z);
    __nv_bfloat16 hw = __float2bfloat16_rn(wv.w);

    __nv_bfloat16 lx = __float2bfloat16_rn(wv.x - __bfloat162float(hx));
    __nv_bfloat16 ly = __float2bfloat16_rn(wv.y - __bfloat162float(hy));
    __nv_bfloat16 lz = __float2bfloat16_rn(wv.z - __bfloat162float(hz));
    __nv_bfloat16 lw = __float2bfloat16_rn(wv.w - __bfloat162float(hw));

    __nv_bfloat162* H = reinterpret_cast<__nv_bfloat162*>(g_Whi);
    __nv_bfloat162* L = reinterpret_cast<__nv_bfloat162*>(g_Wlo);
    __nv_bfloat162 p;
    p.x = hx; p.y = hy; H[(size_t)tid * 2 + 0] = p;
    p.x = hz; p.y = hw; H[(size_t)tid * 2 + 1] = p;
    p.x = lx; p.y = ly; L[(size_t)tid * 2 + 0] = p;
    p.x = lz; p.y = lw; L[(size_t)tid * 2 + 1] = p;
}

// ---------------------------------------------------------------------------
// Load one stage: 4 tiles (Ahi, Alo, Bhi, Blo), each 128x64 bf16, SW128.
// ---------------------------------------------------------------------------
__device__ __forceinline__ void load_stage(uint32_t sb, int kc, int bm, int bn,
                                           int tid) {
    const int kk = kc * BK;
    #pragma unroll
    for (int j = 0; j < 4; ++j) {
        const int i = tid + j * 256;            // 0..1023
        const int row = i >> 3, c16 = i & 7;
        const uint32_t sw = swz(row, c16 * 16);
        const size_t gA = (size_t)(bm + row) * IN_F + kk + c16 * 8;
        const size_t gB = (size_t)(bn + row) * IN_F + kk + c16 * 8;
        cp16(sb + OFF_AHI + sw, g_Xhi + gA);
        cp16(sb + OFF_ALO + sw, g_Xlo + gA);
        cp16(sb + OFF_BHI + sw, g_Whi + gB);
        cp16(sb + OFF_BLO + sw, g_Wlo + gB);
    }
    CP_COMMIT();
}

// ---------------------------------------------------------------------------
// GEMM: fp32 acc in registers; per K-chunk 3 split-terms reuse one stage.
// TERM-MAJOR MMA ordering: 16 independent accumulators between revisits of
// the same acc -> no HMMA RAW stalls.
// ---------------------------------------------------------------------------
__global__ __launch_bounds__(256, 1)
void gemm_mma_kernel(const float* __restrict__ bias, float* __restrict__ Y) {
    extern __shared__ char smem[];
    const int tid = threadIdx.x;
    const int wid = tid >> 5;
    const int lid = tid & 31;
    const int wm = wid & 3;          // warp m index (0..3)
    const int wn = wid >> 2;         // warp n index (0..1)
    const int bm = blockIdx.x * BM;  // m fast -> W tiles shared across wave
    const int bn = blockIdx.y * BN;

    const uint32_t tiles = (smem_u32(smem) + 127u) & ~127u;

    float acc[2][8][4];
    #pragma unroll
    for (int i = 0; i < 2; ++i)
        #pragma unroll
        for (int j = 0; j < 8; ++j)
            #pragma unroll
            for (int k = 0; k < 4; ++k) acc[i][j][k] = 0.0f;

    // Prologue: fill STAGES-1 stages
    #pragma unroll
    for (int s = 0; s < STAGES - 1; ++s)
        load_stage(tiles + s * STAGE_BYTES, s, bm, bn, tid);

    // Per-thread fragment coordinates (swizzle XOR is colb-independent)
    const int arow = wm * 32 + (lid & 15);                     // + im*16
    const int asel = (lid >> 4) << 4;                          // 0 or 16 B
    const int brow = wn * 64 + ((lid >> 4) << 3) + (lid & 7);  // + j2*16
    const int bsel = ((lid >> 3) & 1) << 4;

    for (int kc = 0; kc < KCHUNKS; ++kc) {
        CP_WAIT();
        __syncthreads();

        const int nc = kc + STAGES - 1;
        if (nc < KCHUNKS)
            load_stage(tiles + (nc % STAGES) * STAGE_BYTES, nc, bm, bn, tid);
        else
            CP_COMMIT();   // keep group count aligned for wait_group

        const uint32_t sb = tiles + (kc % STAGES) * STAGE_BYTES;

        #pragma unroll
        for (int ks = 0; ks < 4; ++ks) {
            uint32_t ah[2][4], al[2][4];
            #pragma unroll
            for (int im = 0; im < 2; ++im) {
                const uint32_t aoff = swz(arow + im * 16, ks * 32 + asel);
                ldsm4(ah[im], sb + OFF_AHI + aoff);
                ldsm4(al[im], sb + OFF_ALO + aoff);
            }
            uint32_t bh[4][4], bl[4][4];
            #pragma unroll
            for (int j2 = 0; j2 < 4; ++j2) {
                const uint32_t boff = swz(brow + j2 * 16, ks * 32 + bsel);
                ldsm4(bh[j2], sb + OFF_BHI + boff);
                ldsm4(bl[j2], sb + OFF_BLO + boff);
            }

            // term 1: hi*hi — 16 independent accumulators
            #pragma unroll
            for (int im = 0; im < 2; ++im)
                #pragma unroll
                for (int jn = 0; jn < 8; ++jn)
                    mma16816(acc[im][jn], ah[im],
                             bh[jn >> 1][(jn & 1) * 2],
                             bh[jn >> 1][(jn & 1) * 2 + 1]);
            // term 2: lo*hi
            #pragma unroll
            for (int im = 0; im < 2; ++im)
                #pragma unroll
                for (int jn = 0; jn < 8; ++jn)
                    mma16816(acc[im][jn], al[im],
                             bh[jn >> 1][(jn & 1) * 2],
                             bh[jn >> 1][(jn & 1) * 2 + 1]);
            // term 3: hi*lo
            #pragma unroll
            for (int im = 0; im < 2; ++im)
                #pragma unroll
                for (int jn = 0; jn < 8; ++jn)
                    mma16816(acc[im][jn], ah[im],
                             bl[jn >> 1][(jn & 1) * 2],
                             bl[jn >> 1][(jn & 1) * 2 + 1]);
        }
    }

    // Epilogue: add bias, store fp32
    const int m0 = bm + wm * 32 + (lid >> 2);
    const int n0 = bn + wn * 64 + (lid & 3) * 2;
    #pragma unroll
    for (int im = 0; im < 2; ++im) {
        #pragma unroll
        for (int jn = 0; jn < 8; ++jn) {
            const int m = m0 + im * 16;
            const int n = n0 + jn * 8;
            const float b0 = __ldg(bias + n);
            const float b1 = __ldg(bias + n + 1);
            float2 v0, v1;
            v0.x = acc[im][jn][0] + b0; v0.y = acc[im][jn][1] + b1;
            v1.x = acc[im][jn][2] + b0; v1.y = acc[im][jn][3] + b1;
            *reinterpret_cast<float2*>(Y + (size_t)m * OUT_F + n)       = v0;
            *reinterpret_cast<float2*>(Y + (size_t)(m + 8) * OUT_F + n) = v1;
        }
    }
}

// ---------------------------------------------------------------------------
// Launch (graph-capturable, alloc-free)
// Inputs (metadata order): x, qweight, scales, zeros, bias, noise
// ---------------------------------------------------------------------------
extern "C" void kernel_launch(void* const* d_in, const int* in_sizes, int n_in,
                              void* d_out, int out_size) {
    const float* x      = (const float*)d_in[0];
    const int*   qw     = (const int*)d_in[1];
    const float* scales = (const float*)d_in[2];
    const float* zeros  = (const float*)d_in[3];
    const float* bias   = (const float*)d_in[4];
    const float* noise  = (const float*)d_in[5];
    float* y = (float*)d_out;

    x_split_kernel<<<16384, 256>>>(reinterpret_cast<const float4*>(x));

    dequant_split_kernel<<<44032, 256>>>(
        reinterpret_cast<const int4*>(qw), scales, zeros,
        reinterpret_cast<const float4*>(noise));

    cudaFuncSetAttribute(gemm_mma_kernel,
                         cudaFuncAttributeMaxDynamicSharedMemorySize, SMEM_BYTES);
    dim3 grid(M_ROWS / BM, OUT_F / BN);   // (32, 86) — m-tile fast
    gemm_mma_kernel<<<grid, 256, SMEM_BYTES>>>(bias, y);
}

// round 11
// speedup vs baseline: 4.6976x; 1.4039x over previous
#include <cuda_runtime.h>
#include <cuda_fp16.h>
#include <stdint.h>

// ---------------------------------------------------------------------------
// Problem constants
// ---------------------------------------------------------------------------
#define IN_F     4096
#define OUT_F    11008
#define M_ROWS   4096
#define N_GROUPS 32
#define ALPHA    0.05f

// GEMM tiling (legacy mma.sync path — tcgen05 unavailable at .target sm_103)
#define BM 128
#define BN 128
#define BK 64                         // fp16 K elems per chunk (128B rows)
#define KCHUNKS (IN_F / BK)           // 64 physical chunks
#define STAGES 4

#define TILE_B   16384                // 128 rows * 128 B
#define OFF_AHI  0
#define OFF_ALO  16384
#define OFF_B    32768
#define STAGE_BYTES (3 * TILE_B)      // 48 KB: Ahi, Alo, B
#define SMEM_BYTES (STAGES * STAGE_BYTES + 256)

// ---------------------------------------------------------------------------
// Operand scratch (static device arrays — alloc-free)
// x split into fp16 hi+lo (x represented to ~2^-21); w rounded once to fp16.
// y = (xh + xl) . wh  -> only w's fp16 rounding contributes error (~2.8e-4).
// ---------------------------------------------------------------------------
__device__ __half g_Xhi[(size_t)M_ROWS * IN_F];
__device__ __half g_Xlo[(size_t)M_ROWS * IN_F];
__device__ __half g_Wh [(size_t)OUT_F * IN_F];

// ---------------------------------------------------------------------------
// PTX helpers (plain-sm_103-safe: cp.async, ldmatrix, mma.sync)
// ---------------------------------------------------------------------------
__device__ __forceinline__ uint32_t smem_u32(const void* p) {
    uint32_t a;
    asm("{ .reg .u64 t; cvta.to.shared.u64 t, %1; cvt.u32.u64 %0, t; }"
        : "=r"(a) : "l"(p));
    return a;
}

__device__ __forceinline__ void cp16(uint32_t dst, const void* src) {
    asm volatile("cp.async.cg.shared.global.L2::128B [%0], [%1], 16;"
                 :: "r"(dst), "l"(src));
}
#define CP_COMMIT() asm volatile("cp.async.commit_group;")
#define CP_WAIT()   asm volatile("cp.async.wait_group %0;" :: "n"(STAGES - 2))

__device__ __forceinline__ void ldsm4(uint32_t* r, uint32_t addr) {
    asm volatile("ldmatrix.sync.aligned.m8n8.x4.shared.b16 {%0,%1,%2,%3}, [%4];"
                 : "=r"(r[0]), "=r"(r[1]), "=r"(r[2]), "=r"(r[3]) : "r"(addr));
}

// fp16 HMMA, fp32 accumulate (non-volatile: pure register op)
__device__ __forceinline__ void mma16816(float* c, const uint32_t* a,
                                         uint32_t b0, uint32_t b1) {
    asm("mma.sync.aligned.m16n8k16.row.col.f32.f16.f16.f32 "
        "{%0,%1,%2,%3}, {%4,%5,%6,%7}, {%8,%9}, {%0,%1,%2,%3};"
        : "+f"(c[0]), "+f"(c[1]), "+f"(c[2]), "+f"(c[3])
        : "r"(a[0]), "r"(a[1]), "r"(a[2]), "r"(a[3]), "r"(b0), "r"(b1));
}

// SW128 swizzle on (row*128 + colb), colb < 128:
// simplifies to row*128 + (colb ^ ((row & 7) << 4))
__device__ __forceinline__ uint32_t swz(int row, int colb) {
    return (uint32_t)(row * 128 + (colb ^ ((row & 7) << 4)));
}

// ---------------------------------------------------------------------------
// Prep 1: split X into fp16 hi + fp16 residual
// ---------------------------------------------------------------------------
__global__ void x_split_kernel(const float4* __restrict__ x4) {
    const int tid = blockIdx.x * blockDim.x + threadIdx.x;
    const float4 v = x4[tid];

    const __half hx = __float2half_rn(v.x);
    const __half hy = __float2half_rn(v.y);
    const __half hz = __float2half_rn(v.z);
    const __half hw = __float2half_rn(v.w);

    const __half lx = __float2half_rn(v.x - __half2float(hx));
    const __half ly = __float2half_rn(v.y - __half2float(hy));
    const __half lz = __float2half_rn(v.z - __half2float(hz));
    const __half lw = __float2half_rn(v.w - __half2float(hw));

    __half2* H = reinterpret_cast<__half2*>(g_Xhi);
    __half2* L = reinterpret_cast<__half2*>(g_Xlo);
    __half2 p;
    p.x = hx; p.y = hy; H[(size_t)tid * 2 + 0] = p;
    p.x = hz; p.y = hw; H[(size_t)tid * 2 + 1] = p;
    p.x = lx; p.y = ly; L[(size_t)tid * 2 + 0] = p;
    p.x = lz; p.y = lw; L[(size_t)tid * 2 + 1] = p;
}

// ---------------------------------------------------------------------------
// Prep 2: grouped dequant + relative noise -> single fp16 weight
// ---------------------------------------------------------------------------
__global__ void dequant_kernel(const int4* __restrict__ q4,
                               const float* __restrict__ scales,
                               const float* __restrict__ zeros,
                               const float4* __restrict__ n4) {
    const int tid = blockIdx.x * blockDim.x + threadIdx.x;
    const int o = tid >> 10;
    const int g = (tid & 1023) >> 5;
    const float s  = scales[o * N_GROUPS + g];
    const float zp = zeros[o * N_GROUPS + g];

    const int4   q  = q4[tid];
    const float4 nz = n4[tid];

    float4 wv;
    wv.x = ((float)q.x - zp) * s;
    wv.y = ((float)q.y - zp) * s;
    wv.z = ((float)q.z - zp) * s;
    wv.w = ((float)q.w - zp) * s;

    wv.x = fmaf(ALPHA * fabsf(wv.x), nz.x, wv.x);
    wv.y = fmaf(ALPHA * fabsf(wv.y), nz.y, wv.y);
    wv.z = fmaf(ALPHA * fabsf(wv.z), nz.z, wv.z);
    wv.w = fmaf(ALPHA * fabsf(wv.w), nz.w, wv.w);

    __half2* H = reinterpret_cast<__half2*>(g_Wh);
    __half2 p;
    p.x = __float2half_rn(wv.x); p.y = __float2half_rn(wv.y);
    H[(size_t)tid * 2 + 0] = p;
    p.x = __float2half_rn(wv.z); p.y = __float2half_rn(wv.w);
    H[(size_t)tid * 2 + 1] = p;
}

// ---------------------------------------------------------------------------
// Load one stage: 3 tiles (Ahi, Alo, B), each 128x64 fp16, SW128.
// 12 x cp16 per thread.
// ---------------------------------------------------------------------------
__device__ __forceinline__ void load_stage(uint32_t sb, int kc, int bm, int bn,
                                           int tid) {
    const int kk = kc * BK;
    #pragma unroll
    for (int j = 0; j < 4; ++j) {
        const int i = tid + j * 256;            // 0..1023
        const int row = i >> 3, c16 = i & 7;
        const uint32_t sw = swz(row, c16 * 16);
        const size_t gA = (size_t)(bm + row) * IN_F + kk + c16 * 8;
        const size_t gB = (size_t)(bn + row) * IN_F + kk + c16 * 8;
        cp16(sb + OFF_AHI + sw, g_Xhi + gA);
        cp16(sb + OFF_ALO + sw, g_Xlo + gA);
        cp16(sb + OFF_B   + sw, g_Wh  + gB);
    }
    CP_COMMIT();
}

// ---------------------------------------------------------------------------
// GEMM: fp32 acc in registers; per K-chunk 2 split-terms share one B tile:
// acc += Ahi*B + Alo*B.
// 8 warps: 4 (m) x 2 (n); warp tile 32m x 64n via m16n8k16.
// Grid: blockIdx.x = m-tile (fast) so a wave shares W tiles in L2.
// ---------------------------------------------------------------------------
__global__ __launch_bounds__(256, 1)
void gemm_mma_kernel(const float* __restrict__ bias, float* __restrict__ Y) {
    extern __shared__ char smem[];
    const int tid = threadIdx.x;
    const int wid = tid >> 5;
    const int lid = tid & 31;
    const int wm = wid & 3;          // warp m index (0..3)
    const int wn = wid >> 2;         // warp n index (0..1)
    const int bm = blockIdx.x * BM;  // m fast -> W tiles shared across wave
    const int bn = blockIdx.y * BN;

    const uint32_t tiles = (smem_u32(smem) + 127u) & ~127u;

    float acc[2][8][4];
    #pragma unroll
    for (int i = 0; i < 2; ++i)
        #pragma unroll
        for (int j = 0; j < 8; ++j)
            #pragma unroll
            for (int k = 0; k < 4; ++k) acc[i][j][k] = 0.0f;

    // Prologue: fill STAGES-1 stages
    #pragma unroll
    for (int s = 0; s < STAGES - 1; ++s)
        load_stage(tiles + s * STAGE_BYTES, s, bm, bn, tid);

    // Per-thread fragment coordinates (swizzle XOR is colb-independent)
    const int arow = wm * 32 + (lid & 15);                     // + im*16
    const int asel = (lid >> 4) << 4;                          // 0 or 16 B
    const int brow = wn * 64 + ((lid >> 4) << 3) + (lid & 7);  // + j2*16
    const int bsel = ((lid >> 3) & 1) << 4;

    for (int kc = 0; kc < KCHUNKS; ++kc) {
        CP_WAIT();
        __syncthreads();

        const int nc = kc + STAGES - 1;
        if (nc < KCHUNKS)
            load_stage(tiles + (nc % STAGES) * STAGE_BYTES, nc, bm, bn, tid);
        else
            CP_COMMIT();   // keep group count aligned for wait_group

        const uint32_t sb = tiles + (kc % STAGES) * STAGE_BYTES;

        #pragma unroll
        for (int ks = 0; ks < 4; ++ks) {
            uint32_t ah[2][4], al[2][4];
            #pragma unroll
            for (int im = 0; im < 2; ++im) {
                const uint32_t aoff = swz(arow + im * 16, ks * 32 + asel);
                ldsm4(ah[im], sb + OFF_AHI + aoff);
                ldsm4(al[im], sb + OFF_ALO + aoff);
            }
            uint32_t b[4][4];
            #pragma unroll
            for (int j2 = 0; j2 < 4; ++j2) {
                const uint32_t boff = swz(brow + j2 * 16, ks * 32 + bsel);
                ldsm4(b[j2], sb + OFF_B + boff);
            }

            // term 1: xh * w
            #pragma unroll
            for (int im = 0; im < 2; ++im)
                #pragma unroll
                for (int jn = 0; jn < 8; ++jn)
                    mma16816(acc[im][jn], ah[im],
                             b[jn >> 1][(jn & 1) * 2],
                             b[jn >> 1][(jn & 1) * 2 + 1]);
            // term 2: xl * w
            #pragma unroll
            for (int im = 0; im < 2; ++im)
                #pragma unroll
                for (int jn = 0; jn < 8; ++jn)
                    mma16816(acc[im][jn], al[im],
                             b[jn >> 1][(jn & 1) * 2],
                             b[jn >> 1][(jn & 1) * 2 + 1]);
        }
    }

    // Epilogue: add bias, store fp32
    const int m0 = bm + wm * 32 + (lid >> 2);
    const int n0 = bn + wn * 64 + (lid & 3) * 2;
    #pragma unroll
    for (int im = 0; im < 2; ++im) {
        #pragma unroll
        for (int jn = 0; jn < 8; ++jn) {
            const int m = m0 + im * 16;
            const int n = n0 + jn * 8;
            const float b0 = __ldg(bias + n);
            const float b1 = __ldg(bias + n + 1);
            float2 v0, v1;
            v0.x = acc[im][jn][0] + b0; v0.y = acc[im][jn][1] + b1;
            v1.x = acc[im][jn][2] + b0; v1.y = acc[im][jn][3] + b1;
            *reinterpret_cast<float2*>(Y + (size_t)m * OUT_F + n)       = v0;
            *reinterpret_cast<float2*>(Y + (size_t)(m + 8) * OUT_F + n) = v1;
        }
    }
}

// ---------------------------------------------------------------------------
// Launch (graph-capturable, alloc-free)
// Inputs (metadata order): x, qweight, scales, zeros, bias, noise
// ---------------------------------------------------------------------------
extern "C" void kernel_launch(void* const* d_in, const int* in_sizes, int n_in,
                              void* d_out, int out_size) {
    const float* x      = (const float*)d_in[0];
    const int*   qw     = (const int*)d_in[1];
    const float* scales = (const float*)d_in[2];
    const float* zeros  = (const float*)d_in[3];
    const float* bias   = (const float*)d_in[4];
    const float* noise  = (const float*)d_in[5];
    float* y = (float*)d_out;

    x_split_kernel<<<16384, 256>>>(reinterpret_cast<const float4*>(x));

    dequant_kernel<<<44032, 256>>>(
        reinterpret_cast<const int4*>(qw), scales, zeros,
        reinterpret_cast<const float4*>(noise));

    cudaFuncSetAttribute(gemm_mma_kernel,
                         cudaFuncAttributeMaxDynamicSharedMemorySize, SMEM_BYTES);
    dim3 grid(M_ROWS / BM, OUT_F / BN);   // (32, 86) — m-tile fast
    gemm_mma_kernel<<<grid, 256, SMEM_BYTES>>>(bias, y);
}

// round 13
// speedup vs baseline: 9.3081x; 1.9815x over previous
#include <cuda_runtime.h>
#include <cuda_fp16.h>
#include <stdint.h>

// ---------------------------------------------------------------------------
// Problem constants
// ---------------------------------------------------------------------------
#define IN_F     4096
#define OUT_F    11008
#define M_ROWS   4096
#define N_GROUPS 32
#define ALPHA    0.05f

// GEMM tiling (legacy mma.sync path — tcgen05 unavailable at .target sm_103)
#define BM 128
#define BN 128
#define BK 64                         // fp16 K elems per chunk (128B rows)
#define KCHUNKS (IN_F / BK)           // 64 physical chunks
#define STAGES 3

#define TILE_B   16384                // 128 rows * 128 B
#define OFF_A    0
#define OFF_B    16384
#define STAGE_BYTES (2 * TILE_B)      // 32 KB: A, B
#define SMEM_BYTES (STAGES * STAGE_BYTES + 256)   // ~96.25 KB -> 2 CTAs/SM

// ---------------------------------------------------------------------------
// Operand scratch (static device arrays — alloc-free)
// Single-rounding fp16 for both x and w. Measured: w-rounding alone gives
// rel_err 1.9e-4; adding x-rounding -> ~2.7e-4 (quadrature), margin ~3.7x.
// ---------------------------------------------------------------------------
__device__ __half g_Xh[(size_t)M_ROWS * IN_F];
__device__ __half g_Wh[(size_t)OUT_F * IN_F];

// ---------------------------------------------------------------------------
// PTX helpers (plain-sm_103-safe: cp.async, ldmatrix, mma.sync)
// ---------------------------------------------------------------------------
__device__ __forceinline__ uint32_t smem_u32(const void* p) {
    uint32_t a;
    asm("{ .reg .u64 t; cvta.to.shared.u64 t, %1; cvt.u32.u64 %0, t; }"
        : "=r"(a) : "l"(p));
    return a;
}

__device__ __forceinline__ void cp16(uint32_t dst, const void* src) {
    asm volatile("cp.async.cg.shared.global.L2::128B [%0], [%1], 16;"
                 :: "r"(dst), "l"(src));
}
#define CP_COMMIT() asm volatile("cp.async.commit_group;")
#define CP_WAIT()   asm volatile("cp.async.wait_group %0;" :: "n"(STAGES - 2))

__device__ __forceinline__ void ldsm4(uint32_t* r, uint32_t addr) {
    asm volatile("ldmatrix.sync.aligned.m8n8.x4.shared.b16 {%0,%1,%2,%3}, [%4];"
                 : "=r"(r[0]), "=r"(r[1]), "=r"(r[2]), "=r"(r[3]) : "r"(addr));
}

// fp16 HMMA, fp32 accumulate (non-volatile: pure register op)
__device__ __forceinline__ void mma16816(float* c, const uint32_t* a,
                                         uint32_t b0, uint32_t b1) {
    asm("mma.sync.aligned.m16n8k16.row.col.f32.f16.f16.f32 "
        "{%0,%1,%2,%3}, {%4,%5,%6,%7}, {%8,%9}, {%0,%1,%2,%3};"
        : "+f"(c[0]), "+f"(c[1]), "+f"(c[2]), "+f"(c[3])
        : "r"(a[0]), "r"(a[1]), "r"(a[2]), "r"(a[3]), "r"(b0), "r"(b1));
}

// SW128 swizzle on (row*128 + colb), colb < 128:
// simplifies to row*128 + (colb ^ ((row & 7) << 4))
__device__ __forceinline__ uint32_t swz(int row, int colb) {
    return (uint32_t)(row * 128 + (colb ^ ((row & 7) << 4)));
}

// ---------------------------------------------------------------------------
// Prep 1: round X to fp16
// ---------------------------------------------------------------------------
__global__ void x_half_kernel(const float4* __restrict__ x4) {
    const int tid = blockIdx.x * blockDim.x + threadIdx.x;
    const float4 v = x4[tid];
    __half2* H = reinterpret_cast<__half2*>(g_Xh);
    __half2 p;
    p.x = __float2half_rn(v.x); p.y = __float2half_rn(v.y);
    H[(size_t)tid * 2 + 0] = p;
    p.x = __float2half_rn(v.z); p.y = __float2half_rn(v.w);
    H[(size_t)tid * 2 + 1] = p;
}

// ---------------------------------------------------------------------------
// Prep 2: grouped dequant + relative noise -> fp16 weight
// ---------------------------------------------------------------------------
__global__ void dequant_kernel(const int4* __restrict__ q4,
                               const float* __restrict__ scales,
                               const float* __restrict__ zeros,
                               const float4* __restrict__ n4) {
    const int tid = blockIdx.x * blockDim.x + threadIdx.x;
    const int o = tid >> 10;
    const int g = (tid & 1023) >> 5;
    const float s  = scales[o * N_GROUPS + g];
    const float zp = zeros[o * N_GROUPS + g];

    const int4   q  = q4[tid];
    const float4 nz = n4[tid];

    float4 wv;
    wv.x = ((float)q.x - zp) * s;
    wv.y = ((float)q.y - zp) * s;
    wv.z = ((float)q.z - zp) * s;
    wv.w = ((float)q.w - zp) * s;

    wv.x = fmaf(ALPHA * fabsf(wv.x), nz.x, wv.x);
    wv.y = fmaf(ALPHA * fabsf(wv.y), nz.y, wv.y);
    wv.z = fmaf(ALPHA * fabsf(wv.z), nz.z, wv.z);
    wv.w = fmaf(ALPHA * fabsf(wv.w), nz.w, wv.w);

    __half2* H = reinterpret_cast<__half2*>(g_Wh);
    __half2 p;
    p.x = __float2half_rn(wv.x); p.y = __float2half_rn(wv.y);
    H[(size_t)tid * 2 + 0] = p;
    p.x = __float2half_rn(wv.z); p.y = __float2half_rn(wv.w);
    H[(size_t)tid * 2 + 1] = p;
}

// ---------------------------------------------------------------------------
// Load one stage: A + B tiles, each 128x64 fp16, SW128. 8 x cp16 per thread.
// ---------------------------------------------------------------------------
__device__ __forceinline__ void load_stage(uint32_t sb, int kc, int bm, int bn,
                                           int tid) {
    const int kk = kc * BK;
    #pragma unroll
    for (int j = 0; j < 4; ++j) {
        const int i = tid + j * 256;            // 0..1023
        const int row = i >> 3, c16 = i & 7;
        const uint32_t sw = swz(row, c16 * 16);
        cp16(sb + OFF_A + sw, g_Xh + (size_t)(bm + row) * IN_F + kk + c16 * 8);
        cp16(sb + OFF_B + sw, g_Wh + (size_t)(bn + row) * IN_F + kk + c16 * 8);
    }
    CP_COMMIT();
}

// ---------------------------------------------------------------------------
// GEMM: plain fp16 x fp16 -> fp32, 1 term.
// 8 warps: 4 (m) x 2 (n); warp tile 32m x 64n via m16n8k16.
// 3 stages x 32 KB -> 2 CTAs/SM to hide sync/pipeline bubbles.
// Grid: blockIdx.x = m-tile (fast) so a wave shares W tiles in L2.
// ---------------------------------------------------------------------------
__global__ __launch_bounds__(256, 2)
void gemm_mma_kernel(const float* __restrict__ bias, float* __restrict__ Y) {
    extern __shared__ char smem[];
    const int tid = threadIdx.x;
    const int wid = tid >> 5;
    const int lid = tid & 31;
    const int wm = wid & 3;          // warp m index (0..3)
    const int wn = wid >> 2;         // warp n index (0..1)
    const int bm = blockIdx.x * BM;  // m fast -> W tiles shared across wave
    const int bn = blockIdx.y * BN;

    const uint32_t tiles = (smem_u32(smem) + 127u) & ~127u;

    float acc[2][8][4];
    #pragma unroll
    for (int i = 0; i < 2; ++i)
        #pragma unroll
        for (int j = 0; j < 8; ++j)
            #pragma unroll
            for (int k = 0; k < 4; ++k) acc[i][j][k] = 0.0f;

    // Prologue: fill STAGES-1 stages
    #pragma unroll
    for (int s = 0; s < STAGES - 1; ++s)
        load_stage(tiles + s * STAGE_BYTES, s, bm, bn, tid);

    // Per-thread fragment coordinates (swizzle XOR is colb-independent)
    const int arow = wm * 32 + (lid & 15);                     // + im*16
    const int asel = (lid >> 4) << 4;                          // 0 or 16 B
    const int brow = wn * 64 + ((lid >> 4) << 3) + (lid & 7);  // + j2*16
    const int bsel = ((lid >> 3) & 1) << 4;

    for (int kc = 0; kc < KCHUNKS; ++kc) {
        CP_WAIT();
        __syncthreads();

        const int nc = kc + STAGES - 1;
        if (nc < KCHUNKS)
            load_stage(tiles + (nc % STAGES) * STAGE_BYTES, nc, bm, bn, tid);
        else
            CP_COMMIT();   // keep group count aligned for wait_group

        const uint32_t sb = tiles + (kc % STAGES) * STAGE_BYTES;

        #pragma unroll
        for (int ks = 0; ks < 4; ++ks) {
            uint32_t a[2][4];
            #pragma unroll
            for (int im = 0; im < 2; ++im)
                ldsm4(a[im], sb + OFF_A + swz(arow + im * 16, ks * 32 + asel));

            uint32_t b[4][4];
            #pragma unroll
            for (int j2 = 0; j2 < 4; ++j2)
                ldsm4(b[j2], sb + OFF_B + swz(brow + j2 * 16, ks * 32 + bsel));

            #pragma unroll
            for (int im = 0; im < 2; ++im)
                #pragma unroll
                for (int jn = 0; jn < 8; ++jn)
                    mma16816(acc[im][jn], a[im],
                             b[jn >> 1][(jn & 1) * 2],
                             b[jn >> 1][(jn & 1) * 2 + 1]);
        }
    }

    // Epilogue: add bias, store fp32
    const int m0 = bm + wm * 32 + (lid >> 2);
    const int n0 = bn + wn * 64 + (lid & 3) * 2;
    #pragma unroll
    for (int im = 0; im < 2; ++im) {
        #pragma unroll
        for (int jn = 0; jn < 8; ++jn) {
            const int m = m0 + im * 16;
            const int n = n0 + jn * 8;
            const float b0 = __ldg(bias + n);
            const float b1 = __ldg(bias + n + 1);
            float2 v0, v1;
            v0.x = acc[im][jn][0] + b0; v0.y = acc[im][jn][1] + b1;
            v1.x = acc[im][jn][2] + b0; v1.y = acc[im][jn][3] + b1;
            *reinterpret_cast<float2*>(Y + (size_t)m * OUT_F + n)       = v0;
            *reinterpret_cast<float2*>(Y + (size_t)(m + 8) * OUT_F + n) = v1;
        }
    }
}

// ---------------------------------------------------------------------------
// Launch (graph-capturable, alloc-free)
// Inputs (metadata order): x, qweight, scales, zeros, bias, noise
// ---------------------------------------------------------------------------
extern "C" void kernel_launch(void* const* d_in, const int* in_sizes, int n_in,
                              void* d_out, int out_size) {
    const float* x      = (const float*)d_in[0];
    const int*   qw     = (const int*)d_in[1];
    const float* scales = (const float*)d_in[2];
    const float* zeros  = (const float*)d_in[3];
    const float* bias   = (const float*)d_in[4];
    const float* noise  = (const float*)d_in[5];
    float* y = (float*)d_out;

    x_half_kernel<<<16384, 256>>>(reinterpret_cast<const float4*>(x));

    dequant_kernel<<<44032, 256>>>(
        reinterpret_cast<const int4*>(qw), scales, zeros,
        reinterpret_cast<const float4*>(noise));

    cudaFuncSetAttribute(gemm_mma_kernel,
                         cudaFuncAttributeMaxDynamicSharedMemorySize, SMEM_BYTES);
    dim3 grid(M_ROWS / BM, OUT_F / BN);   // (32, 86) — m-tile fast
    gemm_mma_kernel<<<grid, 256, SMEM_BYTES>>>(bias, y);
}